// round 14
// baseline (speedup 1.0000x reference)
#include <cuda_runtime.h>
#include <cuda_bf16.h>
#include <math.h>
#include <stdint.h>

// Problem dims
#define QL 2048
#define CTX 2048
#define HDIM 4096
#define NH 32
#define NKV 8
#define HD 128
#define KVLEN (CTX + QL)          // 4096
#define KVSTRIDE (KVLEN * HD)     // elements per kv head

#define QSCALE (0.08838834764831845f * 1.4426950408889634f)   // (1/sqrt(128))*log2(e)

// ---------------------------------------------------------------------------
// Scratch (__device__ globals; allocation-free rule)
// ---------------------------------------------------------------------------
__device__ float g_Q[(size_t)QL * HDIM];
__device__ float g_K[(size_t)NKV * KVLEN * HD];
__device__ float g_A[(size_t)QL * HDIM];          // attention out (fp32)

// int8 limbs + per-row scales
__device__ int8_t g_hid1[(size_t)QL * HDIM],  g_hid2[(size_t)QL * HDIM];
__device__ int8_t g_tgt1[(size_t)CTX * HDIM], g_tgt2[(size_t)CTX * HDIM];
__device__ int8_t g_Wq1[(size_t)HDIM * HDIM], g_Wq2[(size_t)HDIM * HDIM];
__device__ int8_t g_Wk1[(size_t)NKV * HD * HDIM], g_Wk2[(size_t)NKV * HD * HDIM];
__device__ int8_t g_Wv1[(size_t)NKV * HD * HDIM], g_Wv2[(size_t)NKV * HD * HDIM];
__device__ int8_t g_Wo1[(size_t)HDIM * HDIM], g_Wo2[(size_t)HDIM * HDIM];
__device__ int8_t g_A1[(size_t)QL * HDIM],  g_A2[(size_t)QL * HDIM];
__device__ float g_sHid[QL], g_sTgt[CTX], g_sWq[HDIM], g_sWk[NKV * HD],
                 g_sWv[NKV * HD], g_sWo[HDIM], g_sA[QL];

// attention operands (bf16, proven path)
__device__ __nv_bfloat16 g_Qh[(size_t)QL * HDIM],  g_Ql[(size_t)QL * HDIM];
__device__ __nv_bfloat16 g_Kh[(size_t)NKV * KVLEN * HD], g_Kl[(size_t)NKV * KVLEN * HD];
__device__ __nv_bfloat16 g_Vh[(size_t)NKV * KVLEN * HD], g_Vl[(size_t)NKV * KVLEN * HD];

// ---------------------------------------------------------------------------
// PTX helpers (base sm_103-legal only: cp.async, ldmatrix, mma.sync)
// ---------------------------------------------------------------------------
__device__ __forceinline__ uint32_t smem_u32(const void* p) {
    uint32_t a;
    asm("{ .reg .u64 t; cvta.to.shared.u64 t, %1; cvt.u32.u64 %0, t; }" : "=r"(a) : "l"(p));
    return a;
}
#define CP_ASYNC16(dst, src) \
    asm volatile("cp.async.cg.shared.global [%0], [%1], 16;" :: "r"(dst), "l"(src))
#define CP_COMMIT() asm volatile("cp.async.commit_group;" ::: "memory")
#define CP_WAIT1()  asm volatile("cp.async.wait_group 1;" ::: "memory")

#define LDSM_X4(r0, r1, r2, r3, addr) \
    asm volatile("ldmatrix.sync.aligned.m8n8.x4.shared.b16 {%0,%1,%2,%3}, [%4];" \
                 : "=r"(r0), "=r"(r1), "=r"(r2), "=r"(r3) : "r"(addr))
#define LDSM_X4_T(r0, r1, r2, r3, addr) \
    asm volatile("ldmatrix.sync.aligned.m8n8.x4.trans.shared.b16 {%0,%1,%2,%3}, [%4];" \
                 : "=r"(r0), "=r"(r1), "=r"(r2), "=r"(r3) : "r"(addr))

#define MMA16816(d, a, b) \
    asm volatile("mma.sync.aligned.m16n8k16.row.col.f32.bf16.bf16.f32 " \
                 "{%0,%1,%2,%3}, {%4,%5,%6,%7}, {%8,%9}, {%0,%1,%2,%3};" \
                 : "+f"((d)[0]), "+f"((d)[1]), "+f"((d)[2]), "+f"((d)[3]) \
                 : "r"((a)[0]), "r"((a)[1]), "r"((a)[2]), "r"((a)[3]), \
                   "r"((b)[0]), "r"((b)[1]))

#define MMAS8(d, a, b) \
    asm volatile("mma.sync.aligned.m16n8k32.row.col.s32.s8.s8.s32 " \
                 "{%0,%1,%2,%3}, {%4,%5,%6,%7}, {%8,%9}, {%0,%1,%2,%3};" \
                 : "+r"((d)[0]), "+r"((d)[1]), "+r"((d)[2]), "+r"((d)[3]) \
                 : "r"((a)[0]), "r"((a)[1]), "r"((a)[2]), "r"((a)[3]), \
                   "r"((b)[0]), "r"((b)[1]))

#define PACK_BF16X2(r, flo, fhi) \
    asm("cvt.rn.bf16x2.f32 %0, %1, %2;" : "=r"(r) : "f"(fhi), "f"(flo))

// ---------------------------------------------------------------------------
// Row quantization: x ~= s * (q1 + q2/256), per 4096-elem row.
// grid = nrows, 256 threads.
// ---------------------------------------------------------------------------
__global__ void quant_rows(const float4* __restrict__ x,
                           char4* __restrict__ l1, char4* __restrict__ l2,
                           float* __restrict__ scales)
{
    const int row = blockIdx.x;
    const int tid = threadIdx.x;
    const float4* xr = x + (size_t)row * 1024;

    float4 v[4];
    float m = 0.0f;
#pragma unroll
    for (int i = 0; i < 4; i++) {
        v[i] = xr[tid + 256 * i];
        m = fmaxf(m, fmaxf(fmaxf(fabsf(v[i].x), fabsf(v[i].y)),
                           fmaxf(fabsf(v[i].z), fabsf(v[i].w))));
    }
#pragma unroll
    for (int o = 16; o >= 1; o >>= 1)
        m = fmaxf(m, __shfl_xor_sync(0xffffffffu, m, o));
    __shared__ float wm[8];
    if ((tid & 31) == 0) wm[tid >> 5] = m;
    __syncthreads();
    m = wm[0];
#pragma unroll
    for (int w = 1; w < 8; w++) m = fmaxf(m, wm[w]);

    const float s = m * (1.0f / 127.0f);
    const float inv = (m > 0.0f) ? 127.0f / m : 0.0f;
    if (tid == 0) scales[row] = s;

#pragma unroll
    for (int i = 0; i < 4; i++) {
        float f[4] = {v[i].x, v[i].y, v[i].z, v[i].w};
        int q1[4], q2[4];
#pragma unroll
        for (int j = 0; j < 4; j++) {
            float t = f[j] * inv;
            q1[j] = (int)rintf(t);
            float r = t - (float)q1[j];
            int q = (int)rintf(r * 256.0f);
            q2[j] = q > 127 ? 127 : (q < -127 ? -127 : q);
        }
        l1[(size_t)row * 1024 + tid + 256 * i] =
            make_char4((signed char)q1[0], (signed char)q1[1],
                       (signed char)q1[2], (signed char)q1[3]);
        l2[(size_t)row * 1024 + tid + 256 * i] =
            make_char4((signed char)q2[0], (signed char)q2[1],
                       (signed char)q2[2], (signed char)q2[3]);
    }
}

// ---------------------------------------------------------------------------
// int8 2-limb IMMA GEMM: C = sa[m]*sb[n]*(ACC1 + ACC2/256)
// CTA tile 128x128, 256 threads (8 warps, warp 64x32), K-chunk 64 bytes,
// 3-stage cp.async pipeline.
// mode 0: C fp32 row-major; mode 1: K layout; mode 2: V bf16 hi/lo split.
// ---------------------------------------------------------------------------
#define I8_TILE_B (128 * 80)          // 10240 per limb tile (64B data + 16 pad)
#define OFF8_A2 I8_TILE_B
#define OFF8_B1 (2 * I8_TILE_B)
#define OFF8_B2 (3 * I8_TILE_B)
#define STG8_B (4 * I8_TILE_B)        // 40960
#define SMEM_I8 (3 * STG8_B)          // 122880

__device__ __forceinline__ void i8_load_stage(
    uint32_t sbase, int stage, int tid,
    const int8_t* a1, const int8_t* a2, const int8_t* b1, const int8_t* b2,
    int bm, int bn, int K, int k0)
{
    const uint32_t st = sbase + stage * STG8_B;
#pragma unroll
    for (int t = 0; t < 8; t++) {
        int idx = tid + 256 * t;          // 0..2047
        int tile = idx >> 9;              // 0..3
        int rem = idx & 511;
        int r = rem >> 2;                 // 0..127
        int c = rem & 3;                  // 16B chunk
        const int8_t* base;
        int grow;
        if (tile == 0)      { base = a1; grow = bm + r; }
        else if (tile == 1) { base = a2; grow = bm + r; }
        else if (tile == 2) { base = b1; grow = bn + r; }
        else                { base = b2; grow = bn + r; }
        const char* src = (const char*)(base + (size_t)grow * K + k0) + c * 16;
        uint32_t dst = st + tile * I8_TILE_B + r * 80 + c * 16;
        CP_ASYNC16(dst, src);
    }
}

__device__ __forceinline__ void imma_core(
    const int8_t* __restrict__ a1, const int8_t* __restrict__ a2,
    const float* __restrict__ sa,
    const int8_t* __restrict__ b1, const int8_t* __restrict__ b2,
    const float* __restrict__ sb,
    int bm, int bn, int K,
    float* __restrict__ C, int ldn, int mode, int pos0)
{
    extern __shared__ char smem[];
    const uint32_t sbase = smem_u32(smem);
    const int tid = threadIdx.x;
    const int wid = tid >> 5;
    const int lane = tid & 31;
    const int wm = (wid >> 2) * 64;       // 2 row groups of 64
    const int wn = (wid & 3) * 32;        // 4 col groups of 32
    const int nch = K / 64;

    int acc1[4][4][4], acc2[4][4][4];
#pragma unroll
    for (int mt = 0; mt < 4; mt++)
#pragma unroll
        for (int nt = 0; nt < 4; nt++)
#pragma unroll
            for (int i = 0; i < 4; i++) { acc1[mt][nt][i] = 0; acc2[mt][nt][i] = 0; }

    i8_load_stage(sbase, 0, tid, a1, a2, b1, b2, bm, bn, K, 0);
    CP_COMMIT();
    i8_load_stage(sbase, 1, tid, a1, a2, b1, b2, bm, bn, K, 64);
    CP_COMMIT();

    int stage = 0;
    for (int c = 0; c < nch; c++) {
        CP_WAIT1();
        __syncthreads();
        if (c + 2 < nch) {
            int s2 = stage + 2; if (s2 >= 3) s2 -= 3;
            i8_load_stage(sbase, s2, tid, a1, a2, b1, b2, bm, bn, K, (c + 2) * 64);
        }
        CP_COMMIT();

        const uint32_t st = sbase + stage * STG8_B;
#pragma unroll
        for (int kg = 0; kg < 2; kg++) {
            const int kb = kg * 32 + (lane >> 4) * 16;   // A byte col
            uint32_t af1[4][4], af2[4][4];
#pragma unroll
            for (int mt = 0; mt < 4; mt++) {
                int row = wm + mt * 16 + (lane & 15);
                uint32_t ad = st + row * 80 + kb;
                LDSM_X4(af1[mt][0], af1[mt][1], af1[mt][2], af1[mt][3], ad);
                LDSM_X4(af2[mt][0], af2[mt][1], af2[mt][2], af2[mt][3], ad + OFF8_A2);
            }
            const int bkb = kg * 32 + ((lane >> 3) & 1) * 16;
#pragma unroll
            for (int p = 0; p < 2; p++) {
                uint32_t bf1[4], bf2[4];
                const int brow = wn + p * 16 + (lane & 7) + (lane >> 4) * 8;
                uint32_t bd = st + OFF8_B1 + brow * 80 + bkb;
                LDSM_X4(bf1[0], bf1[1], bf1[2], bf1[3], bd);
                LDSM_X4(bf2[0], bf2[1], bf2[2], bf2[3], bd + (OFF8_B2 - OFF8_B1));
                // pass 1: q1*q1 -> acc1
#pragma unroll
                for (int mt = 0; mt < 4; mt++) {
                    MMAS8(acc1[mt][2 * p],     af1[mt], &bf1[0]);
                    MMAS8(acc1[mt][2 * p + 1], af1[mt], &bf1[2]);
                }
                // pass 2: q1*q2 -> acc2
#pragma unroll
                for (int mt = 0; mt < 4; mt++) {
                    MMAS8(acc2[mt][2 * p],     af1[mt], &bf2[0]);
                    MMAS8(acc2[mt][2 * p + 1], af1[mt], &bf2[2]);
                }
                // pass 3: q2*q1 -> acc2
#pragma unroll
                for (int mt = 0; mt < 4; mt++) {
                    MMAS8(acc2[mt][2 * p],     af2[mt], &bf1[0]);
                    MMAS8(acc2[mt][2 * p + 1], af2[mt], &bf1[2]);
                }
            }
        }
        stage++; if (stage >= 3) stage = 0;
        __syncthreads();
    }

    // Epilogue: rank-1 scaling
#pragma unroll
    for (int mt = 0; mt < 4; mt++) {
        const int row = bm + wm + mt * 16 + (lane >> 2);
        const float sa0 = __ldg(sa + row);
        const float sa1 = __ldg(sa + row + 8);
#pragma unroll
        for (int nt = 0; nt < 4; nt++) {
            const int col = bn + wn + nt * 8 + (lane & 3) * 2;
            const float sb0 = __ldg(sb + col);
            const float sb1 = __ldg(sb + col + 1);
            float f0 = ((float)acc1[mt][nt][0] + (float)acc2[mt][nt][0] * 0.00390625f) * sa0 * sb0;
            float f1 = ((float)acc1[mt][nt][1] + (float)acc2[mt][nt][1] * 0.00390625f) * sa0 * sb1;
            float f2 = ((float)acc1[mt][nt][2] + (float)acc2[mt][nt][2] * 0.00390625f) * sa1 * sb0;
            float f3 = ((float)acc1[mt][nt][3] + (float)acc2[mt][nt][3] * 0.00390625f) * sa1 * sb1;
            if (mode == 0) {
                *(float2*)(C + (size_t)row * ldn + col) = make_float2(f0, f1);
                *(float2*)(C + (size_t)(row + 8) * ldn + col) = make_float2(f2, f3);
            } else if (mode == 1) {
                const int head = col >> 7;
                const int hd = col & 127;
                float* base = C + (size_t)head * KVSTRIDE + hd;
                *(float2*)(base + (size_t)(pos0 + row) * HD) = make_float2(f0, f1);
                *(float2*)(base + (size_t)(pos0 + row + 8) * HD) = make_float2(f2, f3);
            } else {
                const int head = col >> 7;
                const int hd = col & 127;
                const size_t e0 = (size_t)head * KVSTRIDE + (size_t)(pos0 + row) * HD + hd;
                const size_t e1 = (size_t)head * KVSTRIDE + (size_t)(pos0 + row + 8) * HD + hd;
                uint32_t h0, h1, l0, l1;
                PACK_BF16X2(h0, f0, f1);
                PACK_BF16X2(h1, f2, f3);
                float r0 = f0 - __uint_as_float(h0 << 16);
                float r1 = f1 - __uint_as_float(h0 & 0xFFFF0000u);
                float r2 = f2 - __uint_as_float(h1 << 16);
                float r3 = f3 - __uint_as_float(h1 & 0xFFFF0000u);
                PACK_BF16X2(l0, r0, r1);
                PACK_BF16X2(l1, r2, r3);
                ((uint32_t*)g_Vh)[e0 >> 1] = h0;
                ((uint32_t*)g_Vl)[e0 >> 1] = l0;
                ((uint32_t*)g_Vh)[e1 >> 1] = h1;
                ((uint32_t*)g_Vl)[e1 >> 1] = l1;
            }
        }
    }
}

// Fused Q + K(ctx,noise) + V(ctx,noise) projections: 1024 CTAs.
__global__ __launch_bounds__(256, 1)
void gemm_qkv_i8(float* __restrict__ Qo, float* __restrict__ Ko)
{
    const int cta = blockIdx.x;
    if (cta < 512) {
        const int bm = (cta >> 5) * 128;
        const int bn = (cta & 31) * 128;
        imma_core(g_hid1, g_hid2, g_sHid, g_Wq1, g_Wq2, g_sWq,
                  bm, bn, HDIM, Qo, HDIM, 0, 0);
    } else {
        const int r = cta - 512;
        const int z = r >> 7;                 // 0..3
        const int bm = ((r >> 3) & 15) * 128;
        const int bn = (r & 7) * 128;
        const int8_t *a1, *a2;
        const float* sa;
        int pos0;
        if (z >> 1) { a1 = g_hid1; a2 = g_hid2; sa = g_sHid; pos0 = CTX; }
        else        { a1 = g_tgt1; a2 = g_tgt2; sa = g_sTgt; pos0 = 0; }
        if (z & 1) {
            imma_core(a1, a2, sa, g_Wv1, g_Wv2, g_sWv, bm, bn, HDIM,
                      nullptr, 0, 2, pos0);
        } else {
            imma_core(a1, a2, sa, g_Wk1, g_Wk2, g_sWk, bm, bn, HDIM,
                      Ko, 0, 1, pos0);
        }
    }
}

// Output projection: 512 CTAs.
__global__ __launch_bounds__(256, 1)
void gemm_out_i8(float* __restrict__ C)
{
    const int bm = blockIdx.y * 128;
    const int bn = blockIdx.x * 128;
    imma_core(g_A1, g_A2, g_sA, g_Wo1, g_Wo2, g_sWo, bm, bn, HDIM, C, HDIM, 0, 0);
}

// ---------------------------------------------------------------------------
// RoPE -> bf16 hi/lo split outputs (Q folds in scale*log2e)
// ---------------------------------------------------------------------------
__global__ void rope_q_split(const float* __restrict__ Q,
                             const float* __restrict__ cosb,
                             const float* __restrict__ sinb,
                             __nv_bfloat16* __restrict__ qh,
                             __nv_bfloat16* __restrict__ ql)
{
    int idx = blockIdx.x * blockDim.x + threadIdx.x;
    int hd = idx & 63;
    int t  = idx >> 6;
    int h  = t & (NH - 1);
    int s  = t >> 5;
    int pos = CTX + s;
    float c1 = cosb[(size_t)pos * HD + hd];
    float s1 = sinb[(size_t)pos * HD + hd];
    float c2 = cosb[(size_t)pos * HD + hd + 64];
    float s2 = sinb[(size_t)pos * HD + hd + 64];
    const float* p = Q + (size_t)s * HDIM + h * HD;
    float x1 = p[hd];
    float x2 = p[hd + 64];
    float y1 = (x1 * c1 - x2 * s1) * QSCALE;
    float y2 = (x2 * c2 + x1 * s2) * QSCALE;
    size_t o1 = (size_t)s * HDIM + h * HD + hd;
    __nv_bfloat16 h1 = __float2bfloat16_rn(y1);
    __nv_bfloat16 h2 = __float2bfloat16_rn(y2);
    qh[o1]      = h1;  ql[o1]      = __float2bfloat16_rn(y1 - __bfloat162float(h1));
    qh[o1 + 64] = h2;  ql[o1 + 64] = __float2bfloat16_rn(y2 - __bfloat162float(h2));
}

__global__ void rope_k_split(const float* __restrict__ Kb,
                             const float* __restrict__ cosb,
                             const float* __restrict__ sinb,
                             __nv_bfloat16* __restrict__ kh,
                             __nv_bfloat16* __restrict__ kl)
{
    int idx = blockIdx.x * blockDim.x + threadIdx.x;
    int hd = idx & 63;
    int t  = idx >> 6;
    int pos = t & (KVLEN - 1);
    int kvh = t >> 12;
    float c1 = cosb[(size_t)pos * HD + hd];
    float s1 = sinb[(size_t)pos * HD + hd];
    float c2 = cosb[(size_t)pos * HD + hd + 64];
    float s2 = sinb[(size_t)pos * HD + hd + 64];
    const float* p = Kb + (size_t)kvh * KVSTRIDE + (size_t)pos * HD;
    float x1 = p[hd];
    float x2 = p[hd + 64];
    float y1 = x1 * c1 - x2 * s1;
    float y2 = x2 * c2 + x1 * s2;
    size_t o1 = (size_t)kvh * KVSTRIDE + (size_t)pos * HD + hd;
    __nv_bfloat16 h1 = __float2bfloat16_rn(y1);
    __nv_bfloat16 h2 = __float2bfloat16_rn(y2);
    kh[o1]      = h1;  kl[o1]      = __float2bfloat16_rn(y1 - __bfloat162float(h1));
    kh[o1 + 64] = h2;  kl[o1 + 64] = __float2bfloat16_rn(y2 - __bfloat162float(h2));
}

// ---------------------------------------------------------------------------
// Tensor-core flash attention (bf16 3-pass split, mma.sync) — proven version;
// epilogue writes fp32 to g_A for int8 O-projection.
// ---------------------------------------------------------------------------
#define BQ 128
#define BKV 64
#define RSTR 272
#define SQ_L 34816
#define SSTG 69632
#define STG_SZ 69632
#define T_KH 0
#define T_KL 17408
#define T_VH 34816
#define T_VL 52224
#define ATTN_SMEM (SSTG + 2 * STG_SZ)

__device__ __forceinline__ void attn_load_kv(
    uint32_t sb, int stage, int tid, int kvh, int kc)
{
    const uint32_t st = sb + SSTG + stage * STG_SZ;
    const size_t base = (size_t)kvh * KVSTRIDE + (size_t)kc * BKV * HD;
    const __nv_bfloat16* srcs[4] = { g_Kh + base, g_Kl + base, g_Vh + base, g_Vl + base };
#pragma unroll
    for (int t = 0; t < 16; t++) {
        int idx = tid + 256 * t;
        int tile = idx >> 10;
        int rem = idx & 1023;
        int r = rem >> 4;
        int c = rem & 15;
        const char* src = (const char*)(srcs[tile] + (size_t)r * HD) + c * 16;
        uint32_t dst = st + tile * 17408 + r * RSTR + c * 16;
        CP_ASYNC16(dst, src);
    }
}

__global__ __launch_bounds__(256, 1)
void attn_mma(const __nv_bfloat16* __restrict__ Qh, const __nv_bfloat16* __restrict__ Ql,
              float* __restrict__ O)
{
    extern __shared__ char smem[];
    const uint32_t sb = smem_u32(smem);
    const int tid = threadIdx.x;
    const int wid = tid >> 5;
    const int lane = tid & 31;
    const int h  = blockIdx.y;
    const int q0 = blockIdx.x * BQ;
    const int kvh = h >> 2;

#pragma unroll
    for (int t = 0; t < 16; t++) {
        int idx = tid + 256 * t;
        int tile = idx >> 11;
        int rem = idx & 2047;
        int r = rem >> 4;
        int c = rem & 15;
        const __nv_bfloat16* base = tile ? Ql : Qh;
        const char* src = (const char*)(base + (size_t)(q0 + r) * HDIM + h * HD) + c * 16;
        uint32_t dst = sb + tile * 34816 + r * RSTR + c * 16;
        CP_ASYNC16(dst, src);
    }
    CP_COMMIT();
    attn_load_kv(sb, 0, tid, kvh, 0);
    CP_COMMIT();

    float o[16][4];
#pragma unroll
    for (int nt = 0; nt < 16; nt++)
#pragma unroll
        for (int i = 0; i < 4; i++) o[nt][i] = 0.0f;
    float m0 = -INFINITY, m1 = -INFINITY, l0 = 0.0f, l1 = 0.0f;

    const int NCH = KVLEN / BKV;
    for (int kc = 0; kc < NCH; kc++) {
        if (kc + 1 < NCH) attn_load_kv(sb, (kc + 1) & 1, tid, kvh, kc + 1);
        CP_COMMIT();
        CP_WAIT1();
        __syncthreads();

        const uint32_t st = sb + SSTG + (kc & 1) * STG_SZ;

        float s[8][4];
#pragma unroll
        for (int nt = 0; nt < 8; nt++)
#pragma unroll
            for (int i = 0; i < 4; i++) s[nt][i] = 0.0f;

#pragma unroll
        for (int d16 = 0; d16 < 8; d16++) {
            uint32_t qhf[4], qlf[4];
            const int arow = wid * 16 + (lane & 15);
            const int acol = d16 * 16 + (lane >> 4) * 8;
            uint32_t aaddr = sb + arow * RSTR + acol * 2;
            LDSM_X4(qhf[0], qhf[1], qhf[2], qhf[3], aaddr);
            LDSM_X4(qlf[0], qlf[1], qlf[2], qlf[3], aaddr + SQ_L);
            const int bcol = d16 * 16 + ((lane >> 3) & 1) * 8;
#pragma unroll
            for (int nt2 = 0; nt2 < 4; nt2++) {
                uint32_t bh[4], bl[4];
                const int brow = nt2 * 16 + (lane & 7) + (lane >> 4) * 8;
                uint32_t baddr = st + T_KH + brow * RSTR + bcol * 2;
                LDSM_X4(bh[0], bh[1], bh[2], bh[3], baddr);
                LDSM_X4(bl[0], bl[1], bl[2], bl[3], baddr + (T_KL - T_KH));
                MMA16816(s[2 * nt2],     qhf, &bh[0]);
                MMA16816(s[2 * nt2 + 1], qhf, &bh[2]);
                MMA16816(s[2 * nt2],     qhf, &bl[0]);
                MMA16816(s[2 * nt2 + 1], qhf, &bl[2]);
                MMA16816(s[2 * nt2],     qlf, &bh[0]);
                MMA16816(s[2 * nt2 + 1], qlf, &bh[2]);
            }
        }

        float mloc0 = -INFINITY, mloc1 = -INFINITY;
#pragma unroll
        for (int nt = 0; nt < 8; nt++) {
            mloc0 = fmaxf(mloc0, fmaxf(s[nt][0], s[nt][1]));
            mloc1 = fmaxf(mloc1, fmaxf(s[nt][2], s[nt][3]));
        }
        mloc0 = fmaxf(mloc0, __shfl_xor_sync(0xffffffffu, mloc0, 1));
        mloc0 = fmaxf(mloc0, __shfl_xor_sync(0xffffffffu, mloc0, 2));
        mloc1 = fmaxf(mloc1, __shfl_xor_sync(0xffffffffu, mloc1, 1));
        mloc1 = fmaxf(mloc1, __shfl_xor_sync(0xffffffffu, mloc1, 2));
        float mn0 = fmaxf(m0, mloc0), mn1 = fmaxf(m1, mloc1);
        float a0 = exp2f(m0 - mn0), a1 = exp2f(m1 - mn1);
        m0 = mn0; m1 = mn1;

        float ll0 = 0.0f, ll1 = 0.0f;
        uint32_t ph[4][4], pl[4][4];
#pragma unroll
        for (int nt = 0; nt < 8; nt++) {
            float p0 = exp2f(s[nt][0] - mn0);
            float p1 = exp2f(s[nt][1] - mn0);
            float p2 = exp2f(s[nt][2] - mn1);
            float p3 = exp2f(s[nt][3] - mn1);
            ll0 += p0 + p1; ll1 += p2 + p3;
            uint32_t hA, hB;
            PACK_BF16X2(hA, p0, p1);
            PACK_BF16X2(hB, p2, p3);
            float r0 = p0 - __uint_as_float(hA << 16);
            float r1 = p1 - __uint_as_float(hA & 0xFFFF0000u);
            float r2 = p2 - __uint_as_float(hB << 16);
            float r3 = p3 - __uint_as_float(hB & 0xFFFF0000u);
            uint32_t lA, lB;
            PACK_BF16X2(lA, r0, r1);
            PACK_BF16X2(lB, r2, r3);
            const int kp = nt >> 1, hi8 = (nt & 1) * 2;
            ph[kp][hi8] = hA; ph[kp][hi8 + 1] = hB;
            pl[kp][hi8] = lA; pl[kp][hi8 + 1] = lB;
        }
        ll0 += __shfl_xor_sync(0xffffffffu, ll0, 1);
        ll0 += __shfl_xor_sync(0xffffffffu, ll0, 2);
        ll1 += __shfl_xor_sync(0xffffffffu, ll1, 1);
        ll1 += __shfl_xor_sync(0xffffffffu, ll1, 2);
        l0 = l0 * a0 + ll0;
        l1 = l1 * a1 + ll1;
#pragma unroll
        for (int nt = 0; nt < 16; nt++) {
            o[nt][0] *= a0; o[nt][1] *= a0;
            o[nt][2] *= a1; o[nt][3] *= a1;
        }

#pragma unroll
        for (int kp = 0; kp < 4; kp++) {
            const int vrow = kp * 16 + (lane & 7) + ((lane >> 3) & 1) * 8;
#pragma unroll
            for (int nt2 = 0; nt2 < 8; nt2++) {
                uint32_t vh[4], vl[4];
                const int vcol = nt2 * 16 + (lane >> 4) * 8;
                uint32_t vaddr = st + T_VH + vrow * RSTR + vcol * 2;
                LDSM_X4_T(vh[0], vh[1], vh[2], vh[3], vaddr);
                LDSM_X4_T(vl[0], vl[1], vl[2], vl[3], vaddr + (T_VL - T_VH));
                MMA16816(o[2 * nt2],     ph[kp], &vh[0]);
                MMA16816(o[2 * nt2 + 1], ph[kp], &vh[2]);
                MMA16816(o[2 * nt2],     ph[kp], &vl[0]);
                MMA16816(o[2 * nt2 + 1], ph[kp], &vl[2]);
                MMA16816(o[2 * nt2],     pl[kp], &vh[0]);
                MMA16816(o[2 * nt2 + 1], pl[kp], &vh[2]);
            }
        }
        __syncthreads();
    }

    const float inv0 = 1.0f / l0, inv1 = 1.0f / l1;
    const int row0 = q0 + wid * 16 + (lane >> 2);
#pragma unroll
    for (int nt = 0; nt < 16; nt++) {
        const int col = nt * 8 + (lane & 3) * 2;
        float* d0 = O + (size_t)row0 * HDIM + h * HD + col;
        float* d1 = O + (size_t)(row0 + 8) * HDIM + h * HD + col;
        *(float2*)d0 = make_float2(o[nt][0] * inv0, o[nt][1] * inv0);
        *(float2*)d1 = make_float2(o[nt][2] * inv1, o[nt][3] * inv1);
    }
}

// ---------------------------------------------------------------------------
// Launch
// ---------------------------------------------------------------------------
extern "C" void kernel_launch(void* const* d_in, const int* in_sizes, int n_in,
                              void* d_out, int out_size)
{
    (void)in_sizes; (void)n_in; (void)out_size;
    const float* hidden = (const float*)d_in[0];
    const float* target = (const float*)d_in[1];
    const float* cosb   = (const float*)d_in[2];
    const float* sinb   = (const float*)d_in[3];
    float* out = (float*)d_out;

    float *Qp, *Kp, *Ap;
    cudaGetSymbolAddress((void**)&Qp, g_Q);
    cudaGetSymbolAddress((void**)&Kp, g_K);
    cudaGetSymbolAddress((void**)&Ap, g_A);

    int8_t *hid1, *hid2, *tgt1, *tgt2, *Wq1, *Wq2, *Wk1, *Wk2, *Wv1, *Wv2,
           *Wo1, *Wo2, *A1, *A2;
    float *sHid, *sTgt, *sWq, *sWk, *sWv, *sWo, *sA;
    cudaGetSymbolAddress((void**)&hid1, g_hid1);
    cudaGetSymbolAddress((void**)&hid2, g_hid2);
    cudaGetSymbolAddress((void**)&tgt1, g_tgt1);
    cudaGetSymbolAddress((void**)&tgt2, g_tgt2);
    cudaGetSymbolAddress((void**)&Wq1, g_Wq1);
    cudaGetSymbolAddress((void**)&Wq2, g_Wq2);
    cudaGetSymbolAddress((void**)&Wk1, g_Wk1);
    cudaGetSymbolAddress((void**)&Wk2, g_Wk2);
    cudaGetSymbolAddress((void**)&Wv1, g_Wv1);
    cudaGetSymbolAddress((void**)&Wv2, g_Wv2);
    cudaGetSymbolAddress((void**)&Wo1, g_Wo1);
    cudaGetSymbolAddress((void**)&Wo2, g_Wo2);
    cudaGetSymbolAddress((void**)&A1, g_A1);
    cudaGetSymbolAddress((void**)&A2, g_A2);
    cudaGetSymbolAddress((void**)&sHid, g_sHid);
    cudaGetSymbolAddress((void**)&sTgt, g_sTgt);
    cudaGetSymbolAddress((void**)&sWq, g_sWq);
    cudaGetSymbolAddress((void**)&sWk, g_sWk);
    cudaGetSymbolAddress((void**)&sWv, g_sWv);
    cudaGetSymbolAddress((void**)&sWo, g_sWo);
    cudaGetSymbolAddress((void**)&sA, g_sA);

    __nv_bfloat16 *Qhp, *Qlp, *Khp, *Klp;
    cudaGetSymbolAddress((void**)&Qhp, g_Qh);
    cudaGetSymbolAddress((void**)&Qlp, g_Ql);
    cudaGetSymbolAddress((void**)&Khp, g_Kh);
    cudaGetSymbolAddress((void**)&Klp, g_Kl);

    cudaFuncSetAttribute(gemm_qkv_i8, cudaFuncAttributeMaxDynamicSharedMemorySize, SMEM_I8);
    cudaFuncSetAttribute(gemm_out_i8, cudaFuncAttributeMaxDynamicSharedMemorySize, SMEM_I8);
    cudaFuncSetAttribute(attn_mma, cudaFuncAttributeMaxDynamicSharedMemorySize, ATTN_SMEM);

    // Quantize inputs + weights (per-row 2-limb int8)
    quant_rows<<<QL, 256>>>((const float4*)hidden, (char4*)hid1, (char4*)hid2, sHid);
    quant_rows<<<CTX, 256>>>((const float4*)target, (char4*)tgt1, (char4*)tgt2, sTgt);
    quant_rows<<<HDIM, 256>>>((const float4*)d_in[4], (char4*)Wq1, (char4*)Wq2, sWq);
    quant_rows<<<NKV * HD, 256>>>((const float4*)d_in[5], (char4*)Wk1, (char4*)Wk2, sWk);
    quant_rows<<<NKV * HD, 256>>>((const float4*)d_in[6], (char4*)Wv1, (char4*)Wv2, sWv);
    quant_rows<<<HDIM, 256>>>((const float4*)d_in[7], (char4*)Wo1, (char4*)Wo2, sWo);

    // All input projections in one launch (1024 CTAs)
    gemm_qkv_i8<<<1024, 256, SMEM_I8>>>(Qp, Kp);

    // RoPE + splits for attention operands (V already split by gemm epilogue)
    rope_q_split<<<(QL * NH * 64) / 256, 256>>>(Qp, cosb, sinb, Qhp, Qlp);
    rope_k_split<<<(NKV * KVLEN * 64) / 256, 256>>>(Kp, cosb, sinb, Khp, Klp);

    // Flash attention (bf16 3-pass); writes fp32 attention output
    attn_mma<<<dim3(QL / BQ, NH), 256, ATTN_SMEM>>>(Qhp, Qlp, Ap);

    // Quantize attention output, then int8 output projection
    quant_rows<<<QL, 256>>>((const float4*)Ap, (char4*)A1, (char4*)A2, sA);
    gemm_out_i8<<<dim3(HDIM / 128, QL / 128), 256, SMEM_I8>>>(out);
}

// round 15
// speedup vs baseline: 1.8708x; 1.8708x over previous
#include <cuda_runtime.h>
#include <cuda_bf16.h>
#include <math.h>
#include <stdint.h>

// Problem dims
#define QL 2048
#define CTX 2048
#define HDIM 4096
#define NH 32
#define NKV 8
#define HD 128
#define KVLEN (CTX + QL)          // 4096
#define KVSTRIDE (KVLEN * HD)     // elements per kv head

#define QSCALE (0.08838834764831845f * 1.4426950408889634f)   // (1/sqrt(128))*log2(e)

// ---------------------------------------------------------------------------
// Scratch (__device__ globals; allocation-free rule)
// ---------------------------------------------------------------------------
__device__ float g_Q[(size_t)QL * HDIM];
__device__ float g_K[(size_t)NKV * KVLEN * HD];

__device__ __nv_bfloat16 g_hidHi[(size_t)QL * HDIM],  g_hidLo[(size_t)QL * HDIM];
__device__ __nv_bfloat16 g_tgtHi[(size_t)CTX * HDIM], g_tgtLo[(size_t)CTX * HDIM];
__device__ __nv_bfloat16 g_WqHi[(size_t)HDIM * HDIM], g_WqLo[(size_t)HDIM * HDIM];
__device__ __nv_bfloat16 g_WkHi[(size_t)NKV * HD * HDIM], g_WkLo[(size_t)NKV * HD * HDIM];
__device__ __nv_bfloat16 g_WvHi[(size_t)NKV * HD * HDIM], g_WvLo[(size_t)NKV * HD * HDIM];
__device__ __nv_bfloat16 g_WoHi[(size_t)HDIM * HDIM], g_WoLo[(size_t)HDIM * HDIM];
__device__ __nv_bfloat16 g_AHi[(size_t)QL * HDIM],  g_ALo[(size_t)QL * HDIM];

__device__ __nv_bfloat16 g_Kh[(size_t)NKV * KVLEN * HD], g_Kl[(size_t)NKV * KVLEN * HD];
__device__ __nv_bfloat16 g_Vh[(size_t)NKV * KVLEN * HD], g_Vl[(size_t)NKV * KVLEN * HD];

// ---------------------------------------------------------------------------
// PTX helpers (base sm_103-legal only: cp.async, ldmatrix, mma.sync)
// ---------------------------------------------------------------------------
__device__ __forceinline__ uint32_t smem_u32(const void* p) {
    uint32_t a;
    asm("{ .reg .u64 t; cvta.to.shared.u64 t, %1; cvt.u32.u64 %0, t; }" : "=r"(a) : "l"(p));
    return a;
}
#define CP_ASYNC16(dst, src) \
    asm volatile("cp.async.cg.shared.global [%0], [%1], 16;" :: "r"(dst), "l"(src))
#define CP_COMMIT() asm volatile("cp.async.commit_group;" ::: "memory")
#define CP_WAIT1()  asm volatile("cp.async.wait_group 1;" ::: "memory")

#define LDSM_X4(r0, r1, r2, r3, addr) \
    asm volatile("ldmatrix.sync.aligned.m8n8.x4.shared.b16 {%0,%1,%2,%3}, [%4];" \
                 : "=r"(r0), "=r"(r1), "=r"(r2), "=r"(r3) : "r"(addr))
#define LDSM_X4_T(r0, r1, r2, r3, addr) \
    asm volatile("ldmatrix.sync.aligned.m8n8.x4.trans.shared.b16 {%0,%1,%2,%3}, [%4];" \
                 : "=r"(r0), "=r"(r1), "=r"(r2), "=r"(r3) : "r"(addr))

#define MMA16816(d, a, b) \
    asm volatile("mma.sync.aligned.m16n8k16.row.col.f32.bf16.bf16.f32 " \
                 "{%0,%1,%2,%3}, {%4,%5,%6,%7}, {%8,%9}, {%0,%1,%2,%3};" \
                 : "+f"((d)[0]), "+f"((d)[1]), "+f"((d)[2]), "+f"((d)[3]) \
                 : "r"((a)[0]), "r"((a)[1]), "r"((a)[2]), "r"((a)[3]), \
                   "r"((b)[0]), "r"((b)[1]))

#define PACK_BF16X2(r, flo, fhi) \
    asm("cvt.rn.bf16x2.f32 %0, %1, %2;" : "=r"(r) : "f"(fhi), "f"(flo))

// split two floats -> (hi bf16x2, lo bf16x2)
__device__ __forceinline__ void bsplit2(float f0, float f1,
                                        uint32_t& hi, uint32_t& lo) {
    PACK_BF16X2(hi, f0, f1);
    float r0 = f0 - __uint_as_float(hi << 16);
    float r1 = f1 - __uint_as_float(hi & 0xFFFF0000u);
    PACK_BF16X2(lo, r0, r1);
}

// ---------------------------------------------------------------------------
// bf16-split HMMA GEMM (champion config: 128x256 CTA tile, 256 threads,
// warp 64x64, K-chunk 32, 3-stage cp.async pipeline).
// mode 0: C row-major [., ldn]
// mode 1: KV fp32 layout C[head][pos0+row][hd]
// mode 2: V bf16 hi/lo split directly to g_Vh/g_Vl
// ---------------------------------------------------------------------------
#define TM 128
#define TN 256
#define TK 32
#define A_TILE_B (128 * 80)
#define B_TILE_B (256 * 80)
#define OFF_ALO A_TILE_B
#define OFF_BHI (2 * A_TILE_B)
#define OFF_BLO (2 * A_TILE_B + B_TILE_B)
#define STG_B (2 * A_TILE_B + 2 * B_TILE_B)   // 61440
#define SMEM_G (3 * STG_B)                // 184320

__device__ __forceinline__ void g_load_stage(
    uint32_t sb, int stage, int tid,
    const __nv_bfloat16* aHi, const __nv_bfloat16* aLo,
    const __nv_bfloat16* bHi, const __nv_bfloat16* bLo,
    int bm, int bn, int K, int k0)
{
    const uint32_t st = sb + stage * STG_B;
#pragma unroll
    for (int t = 0; t < 12; t++) {
        int idx = tid + 256 * t;
        const __nv_bfloat16* base;
        int grow, r;
        uint32_t toff;
        if (idx < 512)       { base = aHi; r = idx >> 2;           grow = bm + r; toff = 0; }
        else if (idx < 1024) { base = aLo; r = (idx - 512) >> 2;   grow = bm + r; toff = OFF_ALO; }
        else if (idx < 2048) { base = bHi; r = (idx - 1024) >> 2;  grow = bn + r; toff = OFF_BHI; }
        else                 { base = bLo; r = (idx - 2048) >> 2;  grow = bn + r; toff = OFF_BLO; }
        int c = idx & 3;
        const char* src = (const char*)(base + (size_t)grow * K + k0 + c * 8);
        uint32_t dst = st + toff + r * 80 + c * 16;
        CP_ASYNC16(dst, src);
    }
}

__device__ __forceinline__ void gemm_core(
    const __nv_bfloat16* __restrict__ aHi, const __nv_bfloat16* __restrict__ aLo,
    const __nv_bfloat16* __restrict__ bHi, const __nv_bfloat16* __restrict__ bLo,
    int bm, int bn, int K,
    float* __restrict__ C, int ldn, int mode, int pos0)
{
    extern __shared__ char smem[];
    const uint32_t sb = smem_u32(smem);
    const int tid = threadIdx.x;
    const int wid = tid >> 5;
    const int lane = tid & 31;
    const int wm = (wid >> 2) * 64;
    const int wn = (wid & 3) * 64;
    const int nch = K / TK;

    float acc[4][8][4];
#pragma unroll
    for (int mt = 0; mt < 4; mt++)
#pragma unroll
        for (int nt = 0; nt < 8; nt++)
#pragma unroll
            for (int i = 0; i < 4; i++) acc[mt][nt][i] = 0.0f;

    g_load_stage(sb, 0, tid, aHi, aLo, bHi, bLo, bm, bn, K, 0);
    CP_COMMIT();
    g_load_stage(sb, 1, tid, aHi, aLo, bHi, bLo, bm, bn, K, TK);
    CP_COMMIT();

    int stage = 0;
    for (int c = 0; c < nch; c++) {
        CP_WAIT1();
        __syncthreads();
        if (c + 2 < nch) {
            int s2 = stage + 2; if (s2 >= 3) s2 -= 3;
            g_load_stage(sb, s2, tid, aHi, aLo, bHi, bLo, bm, bn, K, (c + 2) * TK);
        }
        CP_COMMIT();

        const uint32_t st = sb + stage * STG_B;
#pragma unroll
        for (int kg = 0; kg < 2; kg++) {
            uint32_t ah[4][4], al[4][4];
            const int acol = kg * 16 + (lane >> 4) * 8;
#pragma unroll
            for (int mt = 0; mt < 4; mt++) {
                int row = wm + mt * 16 + (lane & 15);
                uint32_t ad = st + row * 80 + acol * 2;
                LDSM_X4(ah[mt][0], ah[mt][1], ah[mt][2], ah[mt][3], ad);
                LDSM_X4(al[mt][0], al[mt][1], al[mt][2], al[mt][3], ad + OFF_ALO);
            }
            const int bcol = kg * 16 + ((lane >> 3) & 1) * 8;
#pragma unroll
            for (int p = 0; p < 4; p++) {
                uint32_t bh[4], bl[4];
                const int brow = wn + p * 16 + (lane & 7) + (lane >> 4) * 8;
                uint32_t bd = st + OFF_BHI + brow * 80 + bcol * 2;
                LDSM_X4(bh[0], bh[1], bh[2], bh[3], bd);
                LDSM_X4(bl[0], bl[1], bl[2], bl[3], bd + (OFF_BLO - OFF_BHI));
#pragma unroll
                for (int mt = 0; mt < 4; mt++) {
                    MMA16816(acc[mt][2 * p],     ah[mt], &bh[0]);
                    MMA16816(acc[mt][2 * p + 1], ah[mt], &bh[2]);
                    MMA16816(acc[mt][2 * p],     ah[mt], &bl[0]);
                    MMA16816(acc[mt][2 * p + 1], ah[mt], &bl[2]);
                    MMA16816(acc[mt][2 * p],     al[mt], &bh[0]);
                    MMA16816(acc[mt][2 * p + 1], al[mt], &bh[2]);
                }
            }
        }
        stage++; if (stage >= 3) stage = 0;
        __syncthreads();
    }

#pragma unroll
    for (int mt = 0; mt < 4; mt++)
#pragma unroll
        for (int nt = 0; nt < 8; nt++) {
            int row = bm + wm + mt * 16 + (lane >> 2);
            int col = bn + wn + nt * 8 + (lane & 3) * 2;
            if (mode == 0) {
                *(float2*)(C + (size_t)row * ldn + col) =
                    make_float2(acc[mt][nt][0], acc[mt][nt][1]);
                *(float2*)(C + (size_t)(row + 8) * ldn + col) =
                    make_float2(acc[mt][nt][2], acc[mt][nt][3]);
            } else if (mode == 1) {
                const int head = col >> 7;
                const int hd = col & 127;
                float* base = C + (size_t)head * KVSTRIDE + hd;
                *(float2*)(base + (size_t)(pos0 + row) * HD) =
                    make_float2(acc[mt][nt][0], acc[mt][nt][1]);
                *(float2*)(base + (size_t)(pos0 + row + 8) * HD) =
                    make_float2(acc[mt][nt][2], acc[mt][nt][3]);
            } else {
                const int head = col >> 7;
                const int hd = col & 127;
                const size_t e0 = (size_t)head * KVSTRIDE + (size_t)(pos0 + row) * HD + hd;
                const size_t e1 = (size_t)head * KVSTRIDE + (size_t)(pos0 + row + 8) * HD + hd;
                uint32_t h0, h1, l0, l1;
                bsplit2(acc[mt][nt][0], acc[mt][nt][1], h0, l0);
                bsplit2(acc[mt][nt][2], acc[mt][nt][3], h1, l1);
                ((uint32_t*)g_Vh)[e0 >> 1] = h0;
                ((uint32_t*)g_Vl)[e0 >> 1] = l0;
                ((uint32_t*)g_Vh)[e1 >> 1] = h1;
                ((uint32_t*)g_Vl)[e1 >> 1] = l1;
            }
        }
}

// Fused Q + K(ctx,noise) + V(ctx,noise) projections: 512 CTAs, 256 threads.
__global__ __launch_bounds__(256, 1)
void gemm_qkv(float* __restrict__ Qo, float* __restrict__ Ko)
{
    const int cta = blockIdx.x;
    if (cta < 256) {
        const int bm = (cta >> 4) * TM;
        const int bn = (cta & 15) * TN;
        gemm_core(g_hidHi, g_hidLo, g_WqHi, g_WqLo, bm, bn, HDIM, Qo, HDIM, 0, 0);
    } else {
        const int r = cta - 256;
        const int z = r >> 6;
        const int bm = ((r >> 2) & 15) * TM;
        const int bn = (r & 3) * TN;
        const __nv_bfloat16 *aHi, *aLo;
        int pos0;
        if (z >> 1) { aHi = g_hidHi; aLo = g_hidLo; pos0 = CTX; }
        else        { aHi = g_tgtHi; aLo = g_tgtLo; pos0 = 0; }
        if (z & 1) {
            gemm_core(aHi, aLo, g_WvHi, g_WvLo, bm, bn, HDIM, nullptr, 0, 2, pos0);
        } else {
            gemm_core(aHi, aLo, g_WkHi, g_WkLo, bm, bn, HDIM, Ko, 0, 1, pos0);
        }
    }
}

// Output projection
__global__ __launch_bounds__(256, 1)
void gemm_out(float* __restrict__ C)
{
    const int bm = blockIdx.y * TM;
    const int bn = blockIdx.x * TN;
    gemm_core(g_AHi, g_ALo, g_WoHi, g_WoLo, bm, bn, HDIM, C, HDIM, 0, 0);
}

// ---------------------------------------------------------------------------
// fp32 -> (bf16 hi, bf16 lo) split
// ---------------------------------------------------------------------------
__global__ void cvt_split(const float4* __restrict__ x,
                          __nv_bfloat162* __restrict__ hi,
                          __nv_bfloat162* __restrict__ lo, int n4)
{
    int i = blockIdx.x * blockDim.x + threadIdx.x;
    if (i >= n4) return;
    float4 v = x[i];
    __nv_bfloat16 hx = __float2bfloat16_rn(v.x);
    __nv_bfloat16 hy = __float2bfloat16_rn(v.y);
    __nv_bfloat16 hz = __float2bfloat16_rn(v.z);
    __nv_bfloat16 hw = __float2bfloat16_rn(v.w);
    __nv_bfloat16 lx = __float2bfloat16_rn(v.x - __bfloat162float(hx));
    __nv_bfloat16 ly = __float2bfloat16_rn(v.y - __bfloat162float(hy));
    __nv_bfloat16 lz = __float2bfloat16_rn(v.z - __bfloat162float(hz));
    __nv_bfloat16 lw = __float2bfloat16_rn(v.w - __bfloat162float(hw));
    hi[2 * i + 0] = __halves2bfloat162(hx, hy);
    hi[2 * i + 1] = __halves2bfloat162(hz, hw);
    lo[2 * i + 0] = __halves2bfloat162(lx, ly);
    lo[2 * i + 1] = __halves2bfloat162(lz, lw);
}

// ---------------------------------------------------------------------------
// RoPE K -> bf16 hi/lo split
// ---------------------------------------------------------------------------
__global__ void rope_k_split(const float* __restrict__ Kb,
                             const float* __restrict__ cosb,
                             const float* __restrict__ sinb,
                             __nv_bfloat16* __restrict__ kh,
                             __nv_bfloat16* __restrict__ kl)
{
    int idx = blockIdx.x * blockDim.x + threadIdx.x;
    int hd = idx & 63;
    int t  = idx >> 6;
    int pos = t & (KVLEN - 1);
    int kvh = t >> 12;
    float c1 = cosb[(size_t)pos * HD + hd];
    float s1 = sinb[(size_t)pos * HD + hd];
    float c2 = cosb[(size_t)pos * HD + hd + 64];
    float s2 = sinb[(size_t)pos * HD + hd + 64];
    const float* p = Kb + (size_t)kvh * KVSTRIDE + (size_t)pos * HD;
    float x1 = p[hd];
    float x2 = p[hd + 64];
    float y1 = x1 * c1 - x2 * s1;
    float y2 = x2 * c2 + x1 * s2;
    size_t o1 = (size_t)kvh * KVSTRIDE + (size_t)pos * HD + hd;
    __nv_bfloat16 h1 = __float2bfloat16_rn(y1);
    __nv_bfloat16 h2 = __float2bfloat16_rn(y2);
    kh[o1]      = h1;  kl[o1]      = __float2bfloat16_rn(y1 - __bfloat162float(h1));
    kh[o1 + 64] = h2;  kl[o1 + 64] = __float2bfloat16_rn(y2 - __bfloat162float(h2));
}

// ---------------------------------------------------------------------------
// Tensor-core flash attention (bf16 3-pass split, mma.sync).
// RoPE-Q + scale + hi/lo split fused into the Q prologue (reads fp32 g_Q).
// ---------------------------------------------------------------------------
#define BQ 128
#define BKV 64
#define RSTR 272
#define SQ_L 34816
#define SSTG 69632
#define STG_SZ 69632
#define T_KH 0
#define T_KL 17408
#define T_VH 34816
#define T_VL 52224
#define ATTN_SMEM (SSTG + 2 * STG_SZ)

__device__ __forceinline__ void attn_load_kv(
    uint32_t sb, int stage, int tid, int kvh, int kc)
{
    const uint32_t st = sb + SSTG + stage * STG_SZ;
    const size_t base = (size_t)kvh * KVSTRIDE + (size_t)kc * BKV * HD;
    const __nv_bfloat16* srcs[4] = { g_Kh + base, g_Kl + base, g_Vh + base, g_Vl + base };
#pragma unroll
    for (int t = 0; t < 16; t++) {
        int idx = tid + 256 * t;
        int tile = idx >> 10;
        int rem = idx & 1023;
        int r = rem >> 4;
        int c = rem & 15;
        const char* src = (const char*)(srcs[tile] + (size_t)r * HD) + c * 16;
        uint32_t dst = st + tile * 17408 + r * RSTR + c * 16;
        CP_ASYNC16(dst, src);
    }
}

__global__ __launch_bounds__(256, 1)
void attn_mma(const float* __restrict__ Q,
              const float* __restrict__ cosb, const float* __restrict__ sinb,
              __nv_bfloat16* __restrict__ OHi, __nv_bfloat16* __restrict__ OLo)
{
    extern __shared__ char smem[];
    const uint32_t sb = smem_u32(smem);
    const int tid = threadIdx.x;
    const int wid = tid >> 5;
    const int lane = tid & 31;
    const int h  = blockIdx.y;
    const int q0 = blockIdx.x * BQ;
    const int kvh = h >> 2;

    // Start KV stage-0 loads first so they overlap the Q prologue math.
    attn_load_kv(sb, 0, tid, kvh, 0);
    CP_COMMIT();

    // Q prologue: fp32 load + RoPE + scale + bf16 hi/lo split -> smem.
    // Tasks: 128 rows x 16 float4-positions in the low half (c4 = 0..60).
#pragma unroll
    for (int t = 0; t < 8; t++) {
        int idx = tid + 256 * t;            // 0..2047
        int r  = idx >> 4;                  // 0..127
        int c4 = (idx & 15) * 4;            // 0..60
        const int pos = CTX + q0 + r;
        const float* qp = Q + (size_t)(q0 + r) * HDIM + h * HD;
        float4 x1 = *(const float4*)(qp + c4);
        float4 x2 = *(const float4*)(qp + c4 + 64);
        float4 c1 = *(const float4*)(cosb + (size_t)pos * HD + c4);
        float4 s1 = *(const float4*)(sinb + (size_t)pos * HD + c4);
        float4 c2 = *(const float4*)(cosb + (size_t)pos * HD + c4 + 64);
        float4 s2 = *(const float4*)(sinb + (size_t)pos * HD + c4 + 64);
        float y1a = (x1.x * c1.x - x2.x * s1.x) * QSCALE;
        float y1b = (x1.y * c1.y - x2.y * s1.y) * QSCALE;
        float y1c = (x1.z * c1.z - x2.z * s1.z) * QSCALE;
        float y1d = (x1.w * c1.w - x2.w * s1.w) * QSCALE;
        float y2a = (x2.x * c2.x + x1.x * s2.x) * QSCALE;
        float y2b = (x2.y * c2.y + x1.y * s2.y) * QSCALE;
        float y2c = (x2.z * c2.z + x1.z * s2.z) * QSCALE;
        float y2d = (x2.w * c2.w + x1.w * s2.w) * QSCALE;
        uint32_t h0, l0, h1, l1, h2, l2, h3, l3;
        bsplit2(y1a, y1b, h0, l0);
        bsplit2(y1c, y1d, h1, l1);
        bsplit2(y2a, y2b, h2, l2);
        bsplit2(y2c, y2d, h3, l3);
        uint32_t d1 = sb + r * RSTR + c4 * 2;          // low half
        uint32_t d2 = d1 + 128;                        // +64 cols * 2B
        asm volatile("st.shared.v2.b32 [%0], {%1, %2};" :: "r"(d1), "r"(h0), "r"(h1) : "memory");
        asm volatile("st.shared.v2.b32 [%0], {%1, %2};" :: "r"(d1 + SQ_L), "r"(l0), "r"(l1) : "memory");
        asm volatile("st.shared.v2.b32 [%0], {%1, %2};" :: "r"(d2), "r"(h2), "r"(h3) : "memory");
        asm volatile("st.shared.v2.b32 [%0], {%1, %2};" :: "r"(d2 + SQ_L), "r"(l2), "r"(l3) : "memory");
    }

    float o[16][4];
#pragma unroll
    for (int nt = 0; nt < 16; nt++)
#pragma unroll
        for (int i = 0; i < 4; i++) o[nt][i] = 0.0f;
    float m0 = -INFINITY, m1 = -INFINITY, l0 = 0.0f, l1 = 0.0f;

    const int NCH = KVLEN / BKV;
    for (int kc = 0; kc < NCH; kc++) {
        if (kc + 1 < NCH) attn_load_kv(sb, (kc + 1) & 1, tid, kvh, kc + 1);
        CP_COMMIT();
        CP_WAIT1();
        __syncthreads();

        const uint32_t st = sb + SSTG + (kc & 1) * STG_SZ;

        float s[8][4];
#pragma unroll
        for (int nt = 0; nt < 8; nt++)
#pragma unroll
            for (int i = 0; i < 4; i++) s[nt][i] = 0.0f;

#pragma unroll
        for (int d16 = 0; d16 < 8; d16++) {
            uint32_t qhf[4], qlf[4];
            const int arow = wid * 16 + (lane & 15);
            const int acol = d16 * 16 + (lane >> 4) * 8;
            uint32_t aaddr = sb + arow * RSTR + acol * 2;
            LDSM_X4(qhf[0], qhf[1], qhf[2], qhf[3], aaddr);
            LDSM_X4(qlf[0], qlf[1], qlf[2], qlf[3], aaddr + SQ_L);
            const int bcol = d16 * 16 + ((lane >> 3) & 1) * 8;
#pragma unroll
            for (int nt2 = 0; nt2 < 4; nt2++) {
                uint32_t bh[4], bl[4];
                const int brow = nt2 * 16 + (lane & 7) + (lane >> 4) * 8;
                uint32_t baddr = st + T_KH + brow * RSTR + bcol * 2;
                LDSM_X4(bh[0], bh[1], bh[2], bh[3], baddr);
                LDSM_X4(bl[0], bl[1], bl[2], bl[3], baddr + (T_KL - T_KH));
                MMA16816(s[2 * nt2],     qhf, &bh[0]);
                MMA16816(s[2 * nt2 + 1], qhf, &bh[2]);
                MMA16816(s[2 * nt2],     qhf, &bl[0]);
                MMA16816(s[2 * nt2 + 1], qhf, &bl[2]);
                MMA16816(s[2 * nt2],     qlf, &bh[0]);
                MMA16816(s[2 * nt2 + 1], qlf, &bh[2]);
            }
        }

        float mloc0 = -INFINITY, mloc1 = -INFINITY;
#pragma unroll
        for (int nt = 0; nt < 8; nt++) {
            mloc0 = fmaxf(mloc0, fmaxf(s[nt][0], s[nt][1]));
            mloc1 = fmaxf(mloc1, fmaxf(s[nt][2], s[nt][3]));
        }
        mloc0 = fmaxf(mloc0, __shfl_xor_sync(0xffffffffu, mloc0, 1));
        mloc0 = fmaxf(mloc0, __shfl_xor_sync(0xffffffffu, mloc0, 2));
        mloc1 = fmaxf(mloc1, __shfl_xor_sync(0xffffffffu, mloc1, 1));
        mloc1 = fmaxf(mloc1, __shfl_xor_sync(0xffffffffu, mloc1, 2));
        float mn0 = fmaxf(m0, mloc0), mn1 = fmaxf(m1, mloc1);
        float a0 = exp2f(m0 - mn0), a1 = exp2f(m1 - mn1);
        m0 = mn0; m1 = mn1;

        float ll0 = 0.0f, ll1 = 0.0f;
        uint32_t ph[4][4], pl[4][4];
#pragma unroll
        for (int nt = 0; nt < 8; nt++) {
            float p0 = exp2f(s[nt][0] - mn0);
            float p1 = exp2f(s[nt][1] - mn0);
            float p2 = exp2f(s[nt][2] - mn1);
            float p3 = exp2f(s[nt][3] - mn1);
            ll0 += p0 + p1; ll1 += p2 + p3;
            uint32_t hA, lA, hB, lB;
            bsplit2(p0, p1, hA, lA);
            bsplit2(p2, p3, hB, lB);
            const int kp = nt >> 1, hi8 = (nt & 1) * 2;
            ph[kp][hi8] = hA; ph[kp][hi8 + 1] = hB;
            pl[kp][hi8] = lA; pl[kp][hi8 + 1] = lB;
        }
        ll0 += __shfl_xor_sync(0xffffffffu, ll0, 1);
        ll0 += __shfl_xor_sync(0xffffffffu, ll0, 2);
        ll1 += __shfl_xor_sync(0xffffffffu, ll1, 1);
        ll1 += __shfl_xor_sync(0xffffffffu, ll1, 2);
        l0 = l0 * a0 + ll0;
        l1 = l1 * a1 + ll1;
#pragma unroll
        for (int nt = 0; nt < 16; nt++) {
            o[nt][0] *= a0; o[nt][1] *= a0;
            o[nt][2] *= a1; o[nt][3] *= a1;
        }

#pragma unroll
        for (int kp = 0; kp < 4; kp++) {
            const int vrow = kp * 16 + (lane & 7) + ((lane >> 3) & 1) * 8;
#pragma unroll
            for (int nt2 = 0; nt2 < 8; nt2++) {
                uint32_t vh[4], vl[4];
                const int vcol = nt2 * 16 + (lane >> 4) * 8;
                uint32_t vaddr = st + T_VH + vrow * RSTR + vcol * 2;
                LDSM_X4_T(vh[0], vh[1], vh[2], vh[3], vaddr);
                LDSM_X4_T(vl[0], vl[1], vl[2], vl[3], vaddr + (T_VL - T_VH));
                MMA16816(o[2 * nt2],     ph[kp], &vh[0]);
                MMA16816(o[2 * nt2 + 1], ph[kp], &vh[2]);
                MMA16816(o[2 * nt2],     ph[kp], &vl[0]);
                MMA16816(o[2 * nt2 + 1], ph[kp], &vl[2]);
                MMA16816(o[2 * nt2],     pl[kp], &vh[0]);
                MMA16816(o[2 * nt2 + 1], pl[kp], &vh[2]);
            }
        }
        __syncthreads();
    }

    const float inv0 = 1.0f / l0, inv1 = 1.0f / l1;
    const int row0 = q0 + wid * 16 + (lane >> 2);
#pragma unroll
    for (int nt = 0; nt < 16; nt++) {
        const int col = nt * 8 + (lane & 3) * 2;
        const size_t idx0 = ((size_t)row0 * HDIM + h * HD + col) >> 1;
        const size_t idx1 = ((size_t)(row0 + 8) * HDIM + h * HD + col) >> 1;
        uint32_t h0, l0w, h1, l1w;
        bsplit2(o[nt][0] * inv0, o[nt][1] * inv0, h0, l0w);
        bsplit2(o[nt][2] * inv1, o[nt][3] * inv1, h1, l1w);
        ((uint32_t*)OHi)[idx0] = h0;
        ((uint32_t*)OLo)[idx0] = l0w;
        ((uint32_t*)OHi)[idx1] = h1;
        ((uint32_t*)OLo)[idx1] = l1w;
    }
}

// ---------------------------------------------------------------------------
// Launch
// ---------------------------------------------------------------------------
extern "C" void kernel_launch(void* const* d_in, const int* in_sizes, int n_in,
                              void* d_out, int out_size)
{
    (void)in_sizes; (void)n_in; (void)out_size;
    const float* hidden = (const float*)d_in[0];
    const float* target = (const float*)d_in[1];
    const float* cosb   = (const float*)d_in[2];
    const float* sinb   = (const float*)d_in[3];
    float* out = (float*)d_out;

    float *Qp, *Kp;
    cudaGetSymbolAddress((void**)&Qp, g_Q);
    cudaGetSymbolAddress((void**)&Kp, g_K);

    __nv_bfloat16 *hidHi, *hidLo, *tgtHi, *tgtLo, *WqHi, *WqLo, *WkHi, *WkLo,
                  *WvHi, *WvLo, *WoHi, *WoLo, *AHi, *ALo, *Khp, *Klp;
    cudaGetSymbolAddress((void**)&hidHi, g_hidHi);
    cudaGetSymbolAddress((void**)&hidLo, g_hidLo);
    cudaGetSymbolAddress((void**)&tgtHi, g_tgtHi);
    cudaGetSymbolAddress((void**)&tgtLo, g_tgtLo);
    cudaGetSymbolAddress((void**)&WqHi, g_WqHi);
    cudaGetSymbolAddress((void**)&WqLo, g_WqLo);
    cudaGetSymbolAddress((void**)&WkHi, g_WkHi);
    cudaGetSymbolAddress((void**)&WkLo, g_WkLo);
    cudaGetSymbolAddress((void**)&WvHi, g_WvHi);
    cudaGetSymbolAddress((void**)&WvLo, g_WvLo);
    cudaGetSymbolAddress((void**)&WoHi, g_WoHi);
    cudaGetSymbolAddress((void**)&WoLo, g_WoLo);
    cudaGetSymbolAddress((void**)&AHi, g_AHi);
    cudaGetSymbolAddress((void**)&ALo, g_ALo);
    cudaGetSymbolAddress((void**)&Khp, g_Kh);
    cudaGetSymbolAddress((void**)&Klp, g_Kl);

    cudaFuncSetAttribute(gemm_qkv, cudaFuncAttributeMaxDynamicSharedMemorySize, SMEM_G);
    cudaFuncSetAttribute(gemm_out, cudaFuncAttributeMaxDynamicSharedMemorySize, SMEM_G);
    cudaFuncSetAttribute(attn_mma, cudaFuncAttributeMaxDynamicSharedMemorySize, ATTN_SMEM);

    // fp32 -> bf16 hi/lo splits
    {
        int n;
        n = QL * HDIM;
        cvt_split<<<n / 4 / 256, 256>>>((const float4*)hidden, (__nv_bfloat162*)hidHi, (__nv_bfloat162*)hidLo, n / 4);
        n = CTX * HDIM;
        cvt_split<<<n / 4 / 256, 256>>>((const float4*)target, (__nv_bfloat162*)tgtHi, (__nv_bfloat162*)tgtLo, n / 4);
        n = HDIM * HDIM;
        cvt_split<<<n / 4 / 256, 256>>>((const float4*)d_in[4], (__nv_bfloat162*)WqHi, (__nv_bfloat162*)WqLo, n / 4);
        n = NKV * HD * HDIM;
        cvt_split<<<n / 4 / 256, 256>>>((const float4*)d_in[5], (__nv_bfloat162*)WkHi, (__nv_bfloat162*)WkLo, n / 4);
        cvt_split<<<n / 4 / 256, 256>>>((const float4*)d_in[6], (__nv_bfloat162*)WvHi, (__nv_bfloat162*)WvLo, n / 4);
        n = HDIM * HDIM;
        cvt_split<<<n / 4 / 256, 256>>>((const float4*)d_in[7], (__nv_bfloat162*)WoHi, (__nv_bfloat162*)WoLo, n / 4);
    }

    // All input projections in one launch (512 CTAs, 256 threads)
    gemm_qkv<<<512, 256, SMEM_G>>>(Qp, Kp);

    // RoPE-K + split (V split by gemm epilogue; RoPE-Q fused into attention)
    rope_k_split<<<(NKV * KVLEN * 64) / 256, 256>>>(Kp, cosb, sinb, Khp, Klp);

    // Flash attention (bf16 3-pass, RoPE-Q fused); writes bf16 hi/lo for Wo
    attn_mma<<<dim3(QL / BQ, NH), 256, ATTN_SMEM>>>(Qp, cosb, sinb, AHi, ALo);

    // Output projection
    gemm_out<<<dim3(HDIM / TN, QL / TM), 256, SMEM_G>>>(out);
}

// round 16
// speedup vs baseline: 1.8884x; 1.0094x over previous
#include <cuda_runtime.h>
#include <cuda_bf16.h>
#include <math.h>
#include <stdint.h>

// Problem dims
#define QL 2048
#define CTX 2048
#define HDIM 4096
#define NH 32
#define NKV 8
#define HD 128
#define KVLEN (CTX + QL)          // 4096
#define KVSTRIDE (KVLEN * HD)     // elements per kv head

#define QSCALE (0.08838834764831845f * 1.4426950408889634f)   // (1/sqrt(128))*log2(e)

// ---------------------------------------------------------------------------
// Scratch (__device__ globals; allocation-free rule)
// ---------------------------------------------------------------------------
__device__ float g_Q[(size_t)QL * HDIM];

__device__ __nv_bfloat16 g_hidHi[(size_t)QL * HDIM],  g_hidLo[(size_t)QL * HDIM];
__device__ __nv_bfloat16 g_tgtHi[(size_t)CTX * HDIM], g_tgtLo[(size_t)CTX * HDIM];
__device__ __nv_bfloat16 g_WqHi[(size_t)HDIM * HDIM], g_WqLo[(size_t)HDIM * HDIM];
__device__ __nv_bfloat16 g_WkHi[(size_t)NKV * HD * HDIM], g_WkLo[(size_t)NKV * HD * HDIM];
__device__ __nv_bfloat16 g_WvHi[(size_t)NKV * HD * HDIM], g_WvLo[(size_t)NKV * HD * HDIM];
__device__ __nv_bfloat16 g_WoHi[(size_t)HDIM * HDIM], g_WoLo[(size_t)HDIM * HDIM];
__device__ __nv_bfloat16 g_AHi[(size_t)QL * HDIM],  g_ALo[(size_t)QL * HDIM];

__device__ __nv_bfloat16 g_Kh[(size_t)NKV * KVLEN * HD], g_Kl[(size_t)NKV * KVLEN * HD];
__device__ __nv_bfloat16 g_Vh[(size_t)NKV * KVLEN * HD], g_Vl[(size_t)NKV * KVLEN * HD];

// ---------------------------------------------------------------------------
// PTX helpers (base sm_103-legal only: cp.async, ldmatrix, mma.sync)
// ---------------------------------------------------------------------------
__device__ __forceinline__ uint32_t smem_u32(const void* p) {
    uint32_t a;
    asm("{ .reg .u64 t; cvta.to.shared.u64 t, %1; cvt.u32.u64 %0, t; }" : "=r"(a) : "l"(p));
    return a;
}
#define CP_ASYNC16(dst, src) \
    asm volatile("cp.async.cg.shared.global [%0], [%1], 16;" :: "r"(dst), "l"(src))
#define CP_COMMIT() asm volatile("cp.async.commit_group;" ::: "memory")
#define CP_WAIT1()  asm volatile("cp.async.wait_group 1;" ::: "memory")

#define LDSM_X4(r0, r1, r2, r3, addr) \
    asm volatile("ldmatrix.sync.aligned.m8n8.x4.shared.b16 {%0,%1,%2,%3}, [%4];" \
                 : "=r"(r0), "=r"(r1), "=r"(r2), "=r"(r3) : "r"(addr))
#define LDSM_X4_T(r0, r1, r2, r3, addr) \
    asm volatile("ldmatrix.sync.aligned.m8n8.x4.trans.shared.b16 {%0,%1,%2,%3}, [%4];" \
                 : "=r"(r0), "=r"(r1), "=r"(r2), "=r"(r3) : "r"(addr))

#define MMA16816(d, a, b) \
    asm volatile("mma.sync.aligned.m16n8k16.row.col.f32.bf16.bf16.f32 " \
                 "{%0,%1,%2,%3}, {%4,%5,%6,%7}, {%8,%9}, {%0,%1,%2,%3};" \
                 : "+f"((d)[0]), "+f"((d)[1]), "+f"((d)[2]), "+f"((d)[3]) \
                 : "r"((a)[0]), "r"((a)[1]), "r"((a)[2]), "r"((a)[3]), \
                   "r"((b)[0]), "r"((b)[1]))

#define PACK_BF16X2(r, flo, fhi) \
    asm("cvt.rn.bf16x2.f32 %0, %1, %2;" : "=r"(r) : "f"(fhi), "f"(flo))

// split two floats -> (hi bf16x2, lo bf16x2)
__device__ __forceinline__ void bsplit2(float f0, float f1,
                                        uint32_t& hi, uint32_t& lo) {
    PACK_BF16X2(hi, f0, f1);
    float r0 = f0 - __uint_as_float(hi << 16);
    float r1 = f1 - __uint_as_float(hi & 0xFFFF0000u);
    PACK_BF16X2(lo, r0, r1);
}

// ---------------------------------------------------------------------------
// bf16-split HMMA GEMM (champion config: 128x256 CTA tile, 256 threads,
// warp 64x64, K-chunk 32, 3-stage cp.async pipeline).
// mode 0: C row-major [., ldn]
// mode 1: K projection with fused RoPE: stage fp32 tile in smem, apply RoPE,
//         write bf16 hi/lo to g_Kh/g_Kl
// mode 2: V bf16 hi/lo split directly to g_Vh/g_Vl
// ---------------------------------------------------------------------------
#define TM 128
#define TN 256
#define TK 32
#define A_TILE_B (128 * 80)
#define B_TILE_B (256 * 80)
#define OFF_ALO A_TILE_B
#define OFF_BHI (2 * A_TILE_B)
#define OFF_BLO (2 * A_TILE_B + B_TILE_B)
#define STG_B (2 * A_TILE_B + 2 * B_TILE_B)   // 61440
#define SMEM_G (3 * STG_B)                // 184320
#define KSTR 264                          // fp32 staging row stride (floats)

__device__ __forceinline__ void g_load_stage(
    uint32_t sb, int stage, int tid,
    const __nv_bfloat16* aHi, const __nv_bfloat16* aLo,
    const __nv_bfloat16* bHi, const __nv_bfloat16* bLo,
    int bm, int bn, int K, int k0)
{
    const uint32_t st = sb + stage * STG_B;
#pragma unroll
    for (int t = 0; t < 12; t++) {
        int idx = tid + 256 * t;
        const __nv_bfloat16* base;
        int grow, r;
        uint32_t toff;
        if (idx < 512)       { base = aHi; r = idx >> 2;           grow = bm + r; toff = 0; }
        else if (idx < 1024) { base = aLo; r = (idx - 512) >> 2;   grow = bm + r; toff = OFF_ALO; }
        else if (idx < 2048) { base = bHi; r = (idx - 1024) >> 2;  grow = bn + r; toff = OFF_BHI; }
        else                 { base = bLo; r = (idx - 2048) >> 2;  grow = bn + r; toff = OFF_BLO; }
        int c = idx & 3;
        const char* src = (const char*)(base + (size_t)grow * K + k0 + c * 8);
        uint32_t dst = st + toff + r * 80 + c * 16;
        CP_ASYNC16(dst, src);
    }
}

__device__ __forceinline__ void gemm_core(
    const __nv_bfloat16* __restrict__ aHi, const __nv_bfloat16* __restrict__ aLo,
    const __nv_bfloat16* __restrict__ bHi, const __nv_bfloat16* __restrict__ bLo,
    int bm, int bn, int K,
    float* __restrict__ C, int ldn, int mode, int pos0,
    const float* __restrict__ cosb, const float* __restrict__ sinb)
{
    extern __shared__ char smem[];
    const uint32_t sb = smem_u32(smem);
    const int tid = threadIdx.x;
    const int wid = tid >> 5;
    const int lane = tid & 31;
    const int wm = (wid >> 2) * 64;
    const int wn = (wid & 3) * 64;
    const int nch = K / TK;

    float acc[4][8][4];
#pragma unroll
    for (int mt = 0; mt < 4; mt++)
#pragma unroll
        for (int nt = 0; nt < 8; nt++)
#pragma unroll
            for (int i = 0; i < 4; i++) acc[mt][nt][i] = 0.0f;

    g_load_stage(sb, 0, tid, aHi, aLo, bHi, bLo, bm, bn, K, 0);
    CP_COMMIT();
    g_load_stage(sb, 1, tid, aHi, aLo, bHi, bLo, bm, bn, K, TK);
    CP_COMMIT();

    int stage = 0;
    for (int c = 0; c < nch; c++) {
        CP_WAIT1();
        __syncthreads();
        if (c + 2 < nch) {
            int s2 = stage + 2; if (s2 >= 3) s2 -= 3;
            g_load_stage(sb, s2, tid, aHi, aLo, bHi, bLo, bm, bn, K, (c + 2) * TK);
        }
        CP_COMMIT();

        const uint32_t st = sb + stage * STG_B;
#pragma unroll
        for (int kg = 0; kg < 2; kg++) {
            uint32_t ah[4][4], al[4][4];
            const int acol = kg * 16 + (lane >> 4) * 8;
#pragma unroll
            for (int mt = 0; mt < 4; mt++) {
                int row = wm + mt * 16 + (lane & 15);
                uint32_t ad = st + row * 80 + acol * 2;
                LDSM_X4(ah[mt][0], ah[mt][1], ah[mt][2], ah[mt][3], ad);
                LDSM_X4(al[mt][0], al[mt][1], al[mt][2], al[mt][3], ad + OFF_ALO);
            }
            const int bcol = kg * 16 + ((lane >> 3) & 1) * 8;
#pragma unroll
            for (int p = 0; p < 4; p++) {
                uint32_t bh[4], bl[4];
                const int brow = wn + p * 16 + (lane & 7) + (lane >> 4) * 8;
                uint32_t bd = st + OFF_BHI + brow * 80 + bcol * 2;
                LDSM_X4(bh[0], bh[1], bh[2], bh[3], bd);
                LDSM_X4(bl[0], bl[1], bl[2], bl[3], bd + (OFF_BLO - OFF_BHI));
#pragma unroll
                for (int mt = 0; mt < 4; mt++) {
                    MMA16816(acc[mt][2 * p],     ah[mt], &bh[0]);
                    MMA16816(acc[mt][2 * p + 1], ah[mt], &bh[2]);
                    MMA16816(acc[mt][2 * p],     ah[mt], &bl[0]);
                    MMA16816(acc[mt][2 * p + 1], ah[mt], &bl[2]);
                    MMA16816(acc[mt][2 * p],     al[mt], &bh[0]);
                    MMA16816(acc[mt][2 * p + 1], al[mt], &bh[2]);
                }
            }
        }
        stage++; if (stage >= 3) stage = 0;
        __syncthreads();
    }

    if (mode == 0) {
#pragma unroll
        for (int mt = 0; mt < 4; mt++)
#pragma unroll
            for (int nt = 0; nt < 8; nt++) {
                int row = bm + wm + mt * 16 + (lane >> 2);
                int col = bn + wn + nt * 8 + (lane & 3) * 2;
                *(float2*)(C + (size_t)row * ldn + col) =
                    make_float2(acc[mt][nt][0], acc[mt][nt][1]);
                *(float2*)(C + (size_t)(row + 8) * ldn + col) =
                    make_float2(acc[mt][nt][2], acc[mt][nt][3]);
            }
    } else if (mode == 2) {
#pragma unroll
        for (int mt = 0; mt < 4; mt++)
#pragma unroll
            for (int nt = 0; nt < 8; nt++) {
                int row = bm + wm + mt * 16 + (lane >> 2);
                int col = bn + wn + nt * 8 + (lane & 3) * 2;
                const int head = col >> 7;
                const int hd = col & 127;
                const size_t e0 = (size_t)head * KVSTRIDE + (size_t)(pos0 + row) * HD + hd;
                const size_t e1 = (size_t)head * KVSTRIDE + (size_t)(pos0 + row + 8) * HD + hd;
                uint32_t h0, h1, l0, l1;
                bsplit2(acc[mt][nt][0], acc[mt][nt][1], h0, l0);
                bsplit2(acc[mt][nt][2], acc[mt][nt][3], h1, l1);
                ((uint32_t*)g_Vh)[e0 >> 1] = h0;
                ((uint32_t*)g_Vl)[e0 >> 1] = l0;
                ((uint32_t*)g_Vh)[e1 >> 1] = h1;
                ((uint32_t*)g_Vl)[e1 >> 1] = l1;
            }
    } else {
        // mode 1: K projection — stage fp32 tile, fused RoPE, bf16 hi/lo out.
        float* stg = (float*)smem;
#pragma unroll
        for (int mt = 0; mt < 4; mt++)
#pragma unroll
            for (int nt = 0; nt < 8; nt++) {
                int r0 = wm + mt * 16 + (lane >> 2);
                int lc = wn + nt * 8 + (lane & 3) * 2;
                stg[r0 * KSTR + lc]     = acc[mt][nt][0];
                stg[r0 * KSTR + lc + 1] = acc[mt][nt][1];
                stg[(r0 + 8) * KSTR + lc]     = acc[mt][nt][2];
                stg[(r0 + 8) * KSTR + lc + 1] = acc[mt][nt][3];
            }
        __syncthreads();
        // RoPE: tasks = 128 rows x 2 heads x 32 hd-pairs = 8192; 32/thread
#pragma unroll
        for (int t = 0; t < 32; t++) {
            int idx = tid + 256 * t;
            int hd = (idx & 31) * 2;          // 0..62 even
            int hl = (idx >> 5) & 1;          // head within tile
            int r  = idx >> 6;                // 0..127
            int lc = hl * 128 + hd;
            float x1a = stg[r * KSTR + lc];
            float x1b = stg[r * KSTR + lc + 1];
            float x2a = stg[r * KSTR + lc + 64];
            float x2b = stg[r * KSTR + lc + 65];
            const int pos = pos0 + bm + r;
            float2 c1 = *(const float2*)(cosb + (size_t)pos * HD + hd);
            float2 s1 = *(const float2*)(sinb + (size_t)pos * HD + hd);
            float2 c2 = *(const float2*)(cosb + (size_t)pos * HD + hd + 64);
            float2 s2 = *(const float2*)(sinb + (size_t)pos * HD + hd + 64);
            float y1a = x1a * c1.x - x2a * s1.x;
            float y1b = x1b * c1.y - x2b * s1.y;
            float y2a = x2a * c2.x + x1a * s2.x;
            float y2b = x2b * c2.y + x1b * s2.y;
            uint32_t h1, l1, h2, l2;
            bsplit2(y1a, y1b, h1, l1);
            bsplit2(y2a, y2b, h2, l2);
            const int head = (bn >> 7) + hl;
            const size_t e1 = (size_t)head * KVSTRIDE + (size_t)pos * HD + hd;
            ((uint32_t*)g_Kh)[e1 >> 1] = h1;
            ((uint32_t*)g_Kl)[e1 >> 1] = l1;
            ((uint32_t*)g_Kh)[(e1 + 64) >> 1] = h2;
            ((uint32_t*)g_Kl)[(e1 + 64) >> 1] = l2;
        }
    }
}

// Fused Q + K(ctx,noise) + V(ctx,noise) projections: 512 CTAs, 256 threads.
__global__ __launch_bounds__(256, 1)
void gemm_qkv(float* __restrict__ Qo,
              const float* __restrict__ cosb, const float* __restrict__ sinb)
{
    const int cta = blockIdx.x;
    if (cta < 256) {
        const int bm = (cta >> 4) * TM;
        const int bn = (cta & 15) * TN;
        gemm_core(g_hidHi, g_hidLo, g_WqHi, g_WqLo, bm, bn, HDIM, Qo, HDIM, 0, 0,
                  nullptr, nullptr);
    } else {
        const int r = cta - 256;
        const int z = r >> 6;
        const int bm = ((r >> 2) & 15) * TM;
        const int bn = (r & 3) * TN;
        const __nv_bfloat16 *aHi, *aLo;
        int pos0;
        if (z >> 1) { aHi = g_hidHi; aLo = g_hidLo; pos0 = CTX; }
        else        { aHi = g_tgtHi; aLo = g_tgtLo; pos0 = 0; }
        if (z & 1) {
            gemm_core(aHi, aLo, g_WvHi, g_WvLo, bm, bn, HDIM, nullptr, 0, 2, pos0,
                      nullptr, nullptr);
        } else {
            gemm_core(aHi, aLo, g_WkHi, g_WkLo, bm, bn, HDIM, nullptr, 0, 1, pos0,
                      cosb, sinb);
        }
    }
}

// Output projection
__global__ __launch_bounds__(256, 1)
void gemm_out(float* __restrict__ C)
{
    const int bm = blockIdx.y * TM;
    const int bn = blockIdx.x * TN;
    gemm_core(g_AHi, g_ALo, g_WoHi, g_WoLo, bm, bn, HDIM, C, HDIM, 0, 0,
              nullptr, nullptr);
}

// ---------------------------------------------------------------------------
// Fused fp32 -> (bf16 hi, bf16 lo) split for all six tensors, one launch.
// Segment boundaries in 256-thread blocks of float4s.
// ---------------------------------------------------------------------------
#define SEG0 8192      // hidden   (QL*HDIM)
#define SEG1 16384     // target   (+CTX*HDIM)
#define SEG2 32768     // Wq       (+HDIM*HDIM)
#define SEG3 36864     // Wk       (+NKV*HD*HDIM)
#define SEG4 40960     // Wv
#define SEG5 57344     // Wo       (+HDIM*HDIM)

__global__ __launch_bounds__(256, 1)
void cvt_all(const float4* __restrict__ hid, const float4* __restrict__ tgt,
             const float4* __restrict__ Wq, const float4* __restrict__ Wk,
             const float4* __restrict__ Wv, const float4* __restrict__ Wo)
{
    const int b = blockIdx.x;
    const float4* src;
    __nv_bfloat162 *hi, *lo;
    int off;
    if (b < SEG0)      { src = hid; hi = (__nv_bfloat162*)g_hidHi; lo = (__nv_bfloat162*)g_hidLo; off = b; }
    else if (b < SEG1) { src = tgt; hi = (__nv_bfloat162*)g_tgtHi; lo = (__nv_bfloat162*)g_tgtLo; off = b - SEG0; }
    else if (b < SEG2) { src = Wq;  hi = (__nv_bfloat162*)g_WqHi;  lo = (__nv_bfloat162*)g_WqLo;  off = b - SEG1; }
    else if (b < SEG3) { src = Wk;  hi = (__nv_bfloat162*)g_WkHi;  lo = (__nv_bfloat162*)g_WkLo;  off = b - SEG2; }
    else if (b < SEG4) { src = Wv;  hi = (__nv_bfloat162*)g_WvHi;  lo = (__nv_bfloat162*)g_WvLo;  off = b - SEG3; }
    else               { src = Wo;  hi = (__nv_bfloat162*)g_WoHi;  lo = (__nv_bfloat162*)g_WoLo;  off = b - SEG4; }

    const int i = off * 256 + threadIdx.x;
    float4 v = src[i];
    uint32_t h0, l0, h1, l1;
    bsplit2(v.x, v.y, h0, l0);
    bsplit2(v.z, v.w, h1, l1);
    ((uint32_t*)hi)[2 * i + 0] = h0;
    ((uint32_t*)hi)[2 * i + 1] = h1;
    ((uint32_t*)lo)[2 * i + 0] = l0;
    ((uint32_t*)lo)[2 * i + 1] = l1;
}

// ---------------------------------------------------------------------------
// Tensor-core flash attention (bf16 3-pass split, mma.sync).
// RoPE-Q + scale + hi/lo split fused into the Q prologue (reads fp32 g_Q).
// ---------------------------------------------------------------------------
#define BQ 128
#define BKV 64
#define RSTR 272
#define SQ_L 34816
#define SSTG 69632
#define STG_SZ 69632
#define T_KH 0
#define T_KL 17408
#define T_VH 34816
#define T_VL 52224
#define ATTN_SMEM (SSTG + 2 * STG_SZ)

__device__ __forceinline__ void attn_load_kv(
    uint32_t sb, int stage, int tid, int kvh, int kc)
{
    const uint32_t st = sb + SSTG + stage * STG_SZ;
    const size_t base = (size_t)kvh * KVSTRIDE + (size_t)kc * BKV * HD;
    const __nv_bfloat16* srcs[4] = { g_Kh + base, g_Kl + base, g_Vh + base, g_Vl + base };
#pragma unroll
    for (int t = 0; t < 16; t++) {
        int idx = tid + 256 * t;
        int tile = idx >> 10;
        int rem = idx & 1023;
        int r = rem >> 4;
        int c = rem & 15;
        const char* src = (const char*)(srcs[tile] + (size_t)r * HD) + c * 16;
        uint32_t dst = st + tile * 17408 + r * RSTR + c * 16;
        CP_ASYNC16(dst, src);
    }
}

__global__ __launch_bounds__(256, 1)
void attn_mma(const float* __restrict__ Q,
              const float* __restrict__ cosb, const float* __restrict__ sinb,
              __nv_bfloat16* __restrict__ OHi, __nv_bfloat16* __restrict__ OLo)
{
    extern __shared__ char smem[];
    const uint32_t sb = smem_u32(smem);
    const int tid = threadIdx.x;
    const int wid = tid >> 5;
    const int lane = tid & 31;
    const int h  = blockIdx.y;
    const int q0 = blockIdx.x * BQ;
    const int kvh = h >> 2;

    attn_load_kv(sb, 0, tid, kvh, 0);
    CP_COMMIT();

    // Q prologue: fp32 load + RoPE + scale + bf16 hi/lo split -> smem.
#pragma unroll
    for (int t = 0; t < 8; t++) {
        int idx = tid + 256 * t;
        int r  = idx >> 4;
        int c4 = (idx & 15) * 4;
        const int pos = CTX + q0 + r;
        const float* qp = Q + (size_t)(q0 + r) * HDIM + h * HD;
        float4 x1 = *(const float4*)(qp + c4);
        float4 x2 = *(const float4*)(qp + c4 + 64);
        float4 c1 = *(const float4*)(cosb + (size_t)pos * HD + c4);
        float4 s1 = *(const float4*)(sinb + (size_t)pos * HD + c4);
        float4 c2 = *(const float4*)(cosb + (size_t)pos * HD + c4 + 64);
        float4 s2 = *(const float4*)(sinb + (size_t)pos * HD + c4 + 64);
        float y1a = (x1.x * c1.x - x2.x * s1.x) * QSCALE;
        float y1b = (x1.y * c1.y - x2.y * s1.y) * QSCALE;
        float y1c = (x1.z * c1.z - x2.z * s1.z) * QSCALE;
        float y1d = (x1.w * c1.w - x2.w * s1.w) * QSCALE;
        float y2a = (x2.x * c2.x + x1.x * s2.x) * QSCALE;
        float y2b = (x2.y * c2.y + x1.y * s2.y) * QSCALE;
        float y2c = (x2.z * c2.z + x1.z * s2.z) * QSCALE;
        float y2d = (x2.w * c2.w + x1.w * s2.w) * QSCALE;
        uint32_t h0, l0, h1, l1, h2, l2, h3, l3;
        bsplit2(y1a, y1b, h0, l0);
        bsplit2(y1c, y1d, h1, l1);
        bsplit2(y2a, y2b, h2, l2);
        bsplit2(y2c, y2d, h3, l3);
        uint32_t d1 = sb + r * RSTR + c4 * 2;
        uint32_t d2 = d1 + 128;
        asm volatile("st.shared.v2.b32 [%0], {%1, %2};" :: "r"(d1), "r"(h0), "r"(h1) : "memory");
        asm volatile("st.shared.v2.b32 [%0], {%1, %2};" :: "r"(d1 + SQ_L), "r"(l0), "r"(l1) : "memory");
        asm volatile("st.shared.v2.b32 [%0], {%1, %2};" :: "r"(d2), "r"(h2), "r"(h3) : "memory");
        asm volatile("st.shared.v2.b32 [%0], {%1, %2};" :: "r"(d2 + SQ_L), "r"(l2), "r"(l3) : "memory");
    }

    float o[16][4];
#pragma unroll
    for (int nt = 0; nt < 16; nt++)
#pragma unroll
        for (int i = 0; i < 4; i++) o[nt][i] = 0.0f;
    float m0 = -INFINITY, m1 = -INFINITY, l0 = 0.0f, l1 = 0.0f;

    const int NCH = KVLEN / BKV;
    for (int kc = 0; kc < NCH; kc++) {
        if (kc + 1 < NCH) attn_load_kv(sb, (kc + 1) & 1, tid, kvh, kc + 1);
        CP_COMMIT();
        CP_WAIT1();
        __syncthreads();

        const uint32_t st = sb + SSTG + (kc & 1) * STG_SZ;

        float s[8][4];
#pragma unroll
        for (int nt = 0; nt < 8; nt++)
#pragma unroll
            for (int i = 0; i < 4; i++) s[nt][i] = 0.0f;

#pragma unroll
        for (int d16 = 0; d16 < 8; d16++) {
            uint32_t qhf[4], qlf[4];
            const int arow = wid * 16 + (lane & 15);
            const int acol = d16 * 16 + (lane >> 4) * 8;
            uint32_t aaddr = sb + arow * RSTR + acol * 2;
            LDSM_X4(qhf[0], qhf[1], qhf[2], qhf[3], aaddr);
            LDSM_X4(qlf[0], qlf[1], qlf[2], qlf[3], aaddr + SQ_L);
            const int bcol = d16 * 16 + ((lane >> 3) & 1) * 8;
#pragma unroll
            for (int nt2 = 0; nt2 < 4; nt2++) {
                uint32_t bh[4], bl[4];
                const int brow = nt2 * 16 + (lane & 7) + (lane >> 4) * 8;
                uint32_t baddr = st + T_KH + brow * RSTR + bcol * 2;
                LDSM_X4(bh[0], bh[1], bh[2], bh[3], baddr);
                LDSM_X4(bl[0], bl[1], bl[2], bl[3], baddr + (T_KL - T_KH));
                MMA16816(s[2 * nt2],     qhf, &bh[0]);
                MMA16816(s[2 * nt2 + 1], qhf, &bh[2]);
                MMA16816(s[2 * nt2],     qhf, &bl[0]);
                MMA16816(s[2 * nt2 + 1], qhf, &bl[2]);
                MMA16816(s[2 * nt2],     qlf, &bh[0]);
                MMA16816(s[2 * nt2 + 1], qlf, &bh[2]);
            }
        }

        float mloc0 = -INFINITY, mloc1 = -INFINITY;
#pragma unroll
        for (int nt = 0; nt < 8; nt++) {
            mloc0 = fmaxf(mloc0, fmaxf(s[nt][0], s[nt][1]));
            mloc1 = fmaxf(mloc1, fmaxf(s[nt][2], s[nt][3]));
        }
        mloc0 = fmaxf(mloc0, __shfl_xor_sync(0xffffffffu, mloc0, 1));
        mloc0 = fmaxf(mloc0, __shfl_xor_sync(0xffffffffu, mloc0, 2));
        mloc1 = fmaxf(mloc1, __shfl_xor_sync(0xffffffffu, mloc1, 1));
        mloc1 = fmaxf(mloc1, __shfl_xor_sync(0xffffffffu, mloc1, 2));
        float mn0 = fmaxf(m0, mloc0), mn1 = fmaxf(m1, mloc1);
        float a0 = exp2f(m0 - mn0), a1 = exp2f(m1 - mn1);
        m0 = mn0; m1 = mn1;

        float ll0 = 0.0f, ll1 = 0.0f;
        uint32_t ph[4][4], pl[4][4];
#pragma unroll
        for (int nt = 0; nt < 8; nt++) {
            float p0 = exp2f(s[nt][0] - mn0);
            float p1 = exp2f(s[nt][1] - mn0);
            float p2 = exp2f(s[nt][2] - mn1);
            float p3 = exp2f(s[nt][3] - mn1);
            ll0 += p0 + p1; ll1 += p2 + p3;
            uint32_t hA, lA, hB, lB;
            bsplit2(p0, p1, hA, lA);
            bsplit2(p2, p3, hB, lB);
            const int kp = nt >> 1, hi8 = (nt & 1) * 2;
            ph[kp][hi8] = hA; ph[kp][hi8 + 1] = hB;
            pl[kp][hi8] = lA; pl[kp][hi8 + 1] = lB;
        }
        ll0 += __shfl_xor_sync(0xffffffffu, ll0, 1);
        ll0 += __shfl_xor_sync(0xffffffffu, ll0, 2);
        ll1 += __shfl_xor_sync(0xffffffffu, ll1, 1);
        ll1 += __shfl_xor_sync(0xffffffffu, ll1, 2);
        l0 = l0 * a0 + ll0;
        l1 = l1 * a1 + ll1;
#pragma unroll
        for (int nt = 0; nt < 16; nt++) {
            o[nt][0] *= a0; o[nt][1] *= a0;
            o[nt][2] *= a1; o[nt][3] *= a1;
        }

#pragma unroll
        for (int kp = 0; kp < 4; kp++) {
            const int vrow = kp * 16 + (lane & 7) + ((lane >> 3) & 1) * 8;
#pragma unroll
            for (int nt2 = 0; nt2 < 8; nt2++) {
                uint32_t vh[4], vl[4];
                const int vcol = nt2 * 16 + (lane >> 4) * 8;
                uint32_t vaddr = st + T_VH + vrow * RSTR + vcol * 2;
                LDSM_X4_T(vh[0], vh[1], vh[2], vh[3], vaddr);
                LDSM_X4_T(vl[0], vl[1], vl[2], vl[3], vaddr + (T_VL - T_VH));
                MMA16816(o[2 * nt2],     ph[kp], &vh[0]);
                MMA16816(o[2 * nt2 + 1], ph[kp], &vh[2]);
                MMA16816(o[2 * nt2],     ph[kp], &vl[0]);
                MMA16816(o[2 * nt2 + 1], ph[kp], &vl[2]);
                MMA16816(o[2 * nt2],     pl[kp], &vh[0]);
                MMA16816(o[2 * nt2 + 1], pl[kp], &vh[2]);
            }
        }
        __syncthreads();
    }

    const float inv0 = 1.0f / l0, inv1 = 1.0f / l1;
    const int row0 = q0 + wid * 16 + (lane >> 2);
#pragma unroll
    for (int nt = 0; nt < 16; nt++) {
        const int col = nt * 8 + (lane & 3) * 2;
        const size_t idx0 = ((size_t)row0 * HDIM + h * HD + col) >> 1;
        const size_t idx1 = ((size_t)(row0 + 8) * HDIM + h * HD + col) >> 1;
        uint32_t h0, l0w, h1, l1w;
        bsplit2(o[nt][0] * inv0, o[nt][1] * inv0, h0, l0w);
        bsplit2(o[nt][2] * inv1, o[nt][3] * inv1, h1, l1w);
        ((uint32_t*)OHi)[idx0] = h0;
        ((uint32_t*)OLo)[idx0] = l0w;
        ((uint32_t*)OHi)[idx1] = h1;
        ((uint32_t*)OLo)[idx1] = l1w;
    }
}

// ---------------------------------------------------------------------------
// Launch
// ---------------------------------------------------------------------------
extern "C" void kernel_launch(void* const* d_in, const int* in_sizes, int n_in,
                              void* d_out, int out_size)
{
    (void)in_sizes; (void)n_in; (void)out_size;
    const float* hidden = (const float*)d_in[0];
    const float* target = (const float*)d_in[1];
    const float* cosb   = (const float*)d_in[2];
    const float* sinb   = (const float*)d_in[3];
    float* out = (float*)d_out;

    float* Qp;
    cudaGetSymbolAddress((void**)&Qp, g_Q);

    __nv_bfloat16 *AHi, *ALo;
    cudaGetSymbolAddress((void**)&AHi, g_AHi);
    cudaGetSymbolAddress((void**)&ALo, g_ALo);

    cudaFuncSetAttribute(gemm_qkv, cudaFuncAttributeMaxDynamicSharedMemorySize, SMEM_G);
    cudaFuncSetAttribute(gemm_out, cudaFuncAttributeMaxDynamicSharedMemorySize, SMEM_G);
    cudaFuncSetAttribute(attn_mma, cudaFuncAttributeMaxDynamicSharedMemorySize, ATTN_SMEM);

    // All fp32 -> bf16 hi/lo splits in one launch
    cvt_all<<<SEG5, 256>>>((const float4*)hidden, (const float4*)target,
                           (const float4*)d_in[4], (const float4*)d_in[5],
                           (const float4*)d_in[6], (const float4*)d_in[7]);

    // All input projections in one launch; K epilogue applies RoPE directly.
    gemm_qkv<<<512, 256, SMEM_G>>>(Qp, cosb, sinb);

    // Flash attention (bf16 3-pass, RoPE-Q fused); writes bf16 hi/lo for Wo
    attn_mma<<<dim3(QL / BQ, NH), 256, ATTN_SMEM>>>(Qp, cosb, sinb, AHi, ALo);

    // Output projection
    gemm_out<<<dim3(HDIM / TN, QL / TM), 256, SMEM_G>>>(out);
}